// round 1
// baseline (speedup 1.0000x reference)
#include <cuda_runtime.h>

#define CIN   32
#define COUT  32
#define HIN   512
#define WIN   512
#define HOUT  510
#define WOUT  510
#define NB    16

#define TOH      8
#define TOW      32
#define THREADS  256
#define XROWS    (TOH + 2)     // 10
#define XCOLS    (TOW + 2)     // 34
#define XSTRIDE  35            // conflict-free stride for the read pattern
#define XTILE    (CIN * XROWS * XSTRIDE)   // 11200 floats
#define WTILE    (CIN * 9 * COUT)          // 9216 floats

__global__ __launch_bounds__(THREADS, 2)
void conv3x3_kernel(const float* __restrict__ x,
                    const float* __restrict__ w,
                    const float* __restrict__ bias,
                    float* __restrict__ out)
{
    extern __shared__ float smem[];
    float* x_s = smem;            // [CIN][XROWS][XSTRIDE]
    float* w_s = smem + XTILE;    // [CIN][9][COUT]

    const int tid = threadIdx.x;
    const int bx  = blockIdx.x;   // 0..15  (W tiles)
    const int by  = blockIdx.y;   // 0..63  (H tiles)
    const int n   = blockIdx.z;   // 0..15

    const int oy0 = by * TOH;
    const int ox0 = bx * TOW;

    // ---- stage weights: w[co][ci][ky][kx] (OIHW) -> w_s[(ci*9+kk)*32 + co]
    for (int idx = tid; idx < WTILE; idx += THREADS) {
        int co = idx / (CIN * 9);
        int r  = idx - co * (CIN * 9);
        int ci = r / 9;
        int kk = r - ci * 9;
        w_s[(ci * 9 + kk) * COUT + co] = w[idx];
    }

    // ---- stage input tile (10 x 34 per channel), zero-filled halo at edges
    const float* xn = x + (size_t)n * CIN * HIN * WIN;
    for (int idx = tid; idx < CIN * XROWS * XCOLS; idx += THREADS) {
        int ci = idx / (XROWS * XCOLS);
        int r  = (idx - ci * (XROWS * XCOLS)) / XCOLS;
        int c  = idx - ci * (XROWS * XCOLS) - r * XCOLS;
        int gy = oy0 + r;
        int gx = ox0 + c;
        float v = 0.0f;
        if (gy < HIN && gx < WIN)
            v = xn[(ci * HIN + gy) * WIN + gx];
        x_s[ci * (XROWS * XSTRIDE) + r * XSTRIDE + c] = v;
    }
    __syncthreads();

    // ---- thread mapping: 4 co-groups (8 co each) x 64 pixel-groups (4 px each)
    const int cg      = tid >> 6;          // 0..3  (uniform within a warp)
    const int g       = tid & 63;
    const int prow    = g >> 3;            // 0..7
    const int pcol    = (g & 7) << 2;      // 0,4,...,28
    const int co_base = cg * 8;

    float acc[8][4];
    #pragma unroll
    for (int i = 0; i < 8; ++i) {
        float b = bias[co_base + i];
        #pragma unroll
        for (int p = 0; p < 4; ++p) acc[i][p] = b;
    }

    const float* xbase = x_s + prow * XSTRIDE + pcol;
    const float* wbase = w_s + co_base;

    #pragma unroll 4
    for (int ci = 0; ci < CIN; ++ci) {
        #pragma unroll
        for (int ky = 0; ky < 3; ++ky) {
            const float* xr = xbase + ci * (XROWS * XSTRIDE) + ky * XSTRIDE;
            float xv[6];
            #pragma unroll
            for (int j = 0; j < 6; ++j) xv[j] = xr[j];

            const float* wp = wbase + (ci * 9 + ky * 3) * COUT;
            #pragma unroll
            for (int kx = 0; kx < 3; ++kx) {
                #pragma unroll
                for (int i = 0; i < 8; ++i) {
                    float wv = wp[kx * COUT + i];
                    #pragma unroll
                    for (int p = 0; p < 4; ++p)
                        acc[i][p] = fmaf(xv[kx + p], wv, acc[i][p]);
                }
            }
        }
    }

    // ---- store (predicated at 510-edges)
    const int oy  = oy0 + prow;
    const int oxb = ox0 + pcol;
    if (oy < HOUT) {
        float* outn = out + (size_t)n * COUT * HOUT * WOUT;
        #pragma unroll
        for (int i = 0; i < 8; ++i) {
            float* orow = outn + (size_t)(co_base + i) * HOUT * WOUT
                               + (size_t)oy * WOUT + oxb;
            #pragma unroll
            for (int p = 0; p < 4; ++p)
                if (oxb + p < WOUT) orow[p] = acc[i][p];
        }
    }
}

extern "C" void kernel_launch(void* const* d_in, const int* in_sizes, int n_in,
                              void* d_out, int out_size)
{
    const float* x    = (const float*)d_in[0];
    const float* w    = (const float*)d_in[1];
    const float* bias = (const float*)d_in[2];
    float*       out  = (float*)d_out;

    const size_t smem_bytes = (size_t)(XTILE + WTILE) * sizeof(float); // 81664 B
    cudaFuncSetAttribute(conv3x3_kernel,
                         cudaFuncAttributeMaxDynamicSharedMemorySize,
                         (int)smem_bytes);

    dim3 grid((WOUT + TOW - 1) / TOW,   // 16
              (HOUT + TOH - 1) / TOH,   // 64
              NB);                      // 16
    conv3x3_kernel<<<grid, THREADS, smem_bytes>>>(x, w, bias, out);
}

// round 2
// speedup vs baseline: 1.1090x; 1.1090x over previous
#include <cuda_runtime.h>
#include <cstdint>

#define CIN   32
#define COUT  32
#define HIN   512
#define WIN   512
#define HOUT  510
#define WOUT  510
#define NB    16

#define TOH      8
#define TOW      32
#define THREADS  256
#define XROWS    (TOH + 2)     // 10
#define XCOLS    (TOW + 2)     // 34
#define XSTRIDE  35            // conflict-free stride for the read pattern
#define XTILE    (CIN * XROWS * XSTRIDE)   // 11200 floats
#define WTILE    (CIN * 9 * COUT)          // 9216 floats

__device__ __forceinline__ uint64_t pack2(float lo, float hi) {
    uint64_t r;
    asm("mov.b64 %0, {%1, %2};" : "=l"(r) : "f"(lo), "f"(hi));
    return r;
}
__device__ __forceinline__ void fma2(uint64_t& d, uint64_t a, uint64_t b) {
    asm("fma.rn.f32x2 %0, %1, %2, %0;" : "+l"(d) : "l"(a), "l"(b));
}
__device__ __forceinline__ void unpack2(uint64_t v, float& lo, float& hi) {
    asm("mov.b64 {%0, %1}, %2;" : "=f"(lo), "=f"(hi) : "l"(v));
}

__global__ __launch_bounds__(THREADS, 2)
void conv3x3_kernel(const float* __restrict__ x,
                    const float* __restrict__ w,
                    const float* __restrict__ bias,
                    float* __restrict__ out)
{
    extern __shared__ float smem[];
    float* x_s = smem;            // [CIN][XROWS][XSTRIDE]
    float* w_s = smem + XTILE;    // [CIN][9][COUT]  (co contiguous, 8B-aligned)

    const int tid = threadIdx.x;
    const int bx  = blockIdx.x;   // 0..15  (W tiles)
    const int by  = blockIdx.y;   // 0..63  (H tiles)
    const int n   = blockIdx.z;   // 0..15

    const int oy0 = by * TOH;
    const int ox0 = bx * TOW;

    // ---- stage weights: w[co][ci][ky][kx] (OIHW) -> w_s[(ci*9+kk)*32 + co]
    for (int idx = tid; idx < WTILE; idx += THREADS) {
        int co = idx / (CIN * 9);
        int r  = idx - co * (CIN * 9);
        int ci = r / 9;
        int kk = r - ci * 9;
        w_s[(ci * 9 + kk) * COUT + co] = w[idx];
    }

    // ---- stage input tile (10 x 34 per channel), zero-filled halo at edges
    const float* xn = x + (size_t)n * CIN * HIN * WIN;
    for (int idx = tid; idx < CIN * XROWS * XCOLS; idx += THREADS) {
        int ci = idx / (XROWS * XCOLS);
        int r  = (idx - ci * (XROWS * XCOLS)) / XCOLS;
        int c  = idx - ci * (XROWS * XCOLS) - r * XCOLS;
        int gy = oy0 + r;
        int gx = ox0 + c;
        float v = 0.0f;
        if (gy < HIN && gx < WIN)
            v = xn[(ci * HIN + gy) * WIN + gx];
        x_s[ci * (XROWS * XSTRIDE) + r * XSTRIDE + c] = v;
    }
    __syncthreads();

    // ---- thread mapping: 4 co-groups (8 co each) x 64 pixel-groups (4 px each)
    const int cg      = tid >> 6;          // uniform within a warp
    const int g       = tid & 63;
    const int prow    = g >> 3;            // 0..7
    const int pcol    = (g & 7) << 2;      // 0,4,...,28
    const int co_base = cg * 8;

    // acc2[j][p]: co pair (co_base+2j, co_base+2j+1) at pixel p  — f32x2 packed
    uint64_t acc2[4][4];
    #pragma unroll
    for (int j = 0; j < 4; ++j) {
        uint64_t b = pack2(bias[co_base + 2 * j], bias[co_base + 2 * j + 1]);
        #pragma unroll
        for (int p = 0; p < 4; ++p) acc2[j][p] = b;
    }

    const float* xbase = x_s + prow * XSTRIDE + pcol;
    const float* wbase = w_s + co_base;

    #pragma unroll 4
    for (int ci = 0; ci < CIN; ++ci) {
        #pragma unroll
        for (int ky = 0; ky < 3; ++ky) {
            const float* xr = xbase + ci * (XROWS * XSTRIDE) + ky * XSTRIDE;
            uint64_t xp[6];
            #pragma unroll
            for (int jj = 0; jj < 6; ++jj) {
                float v = xr[jj];
                xp[jj] = pack2(v, v);      // splat for co-pair packing
            }

            const float* wp = wbase + (ci * 9 + ky * 3) * COUT;
            #pragma unroll
            for (int kx = 0; kx < 3; ++kx) {
                uint64_t wv[4];
                #pragma unroll
                for (int j = 0; j < 4; ++j)  // LDS.64 broadcast (co pair)
                    wv[j] = *reinterpret_cast<const uint64_t*>(wp + kx * COUT + 2 * j);
                #pragma unroll
                for (int j = 0; j < 4; ++j)
                    #pragma unroll
                    for (int p = 0; p < 4; ++p)
                        fma2(acc2[j][p], xp[kx + p], wv[j]);
            }
        }
    }

    // ---- store (predicated at 510-edges)
    const int oy  = oy0 + prow;
    const int oxb = ox0 + pcol;
    if (oy < HOUT) {
        float* outn = out + (size_t)n * COUT * HOUT * WOUT;
        #pragma unroll
        for (int j = 0; j < 4; ++j) {
            float* orow0 = outn + (size_t)(co_base + 2 * j) * HOUT * WOUT
                                + (size_t)oy * WOUT + oxb;
            float* orow1 = orow0 + (size_t)HOUT * WOUT;
            #pragma unroll
            for (int p = 0; p < 4; ++p) {
                float lo, hi;
                unpack2(acc2[j][p], lo, hi);
                if (oxb + p < WOUT) {
                    orow0[p] = lo;
                    orow1[p] = hi;
                }
            }
        }
    }
}

extern "C" void kernel_launch(void* const* d_in, const int* in_sizes, int n_in,
                              void* d_out, int out_size)
{
    const float* x    = (const float*)d_in[0];
    const float* w    = (const float*)d_in[1];
    const float* bias = (const float*)d_in[2];
    float*       out  = (float*)d_out;

    const size_t smem_bytes = (size_t)(XTILE + WTILE) * sizeof(float); // 81664 B
    cudaFuncSetAttribute(conv3x3_kernel,
                         cudaFuncAttributeMaxDynamicSharedMemorySize,
                         (int)smem_bytes);

    dim3 grid((WOUT + TOW - 1) / TOW,   // 16
              (HOUT + TOH - 1) / TOH,   // 64
              NB);                      // 16
    conv3x3_kernel<<<grid, THREADS, smem_bytes>>>(x, w, bias, out);
}

// round 5
// speedup vs baseline: 1.9388x; 1.7483x over previous
#include <cuda_runtime.h>
#include <cuda_bf16.h>
#include <cstdint>

// ---------------- problem dims ----------------
#define CIN   32
#define COUT  32
#define HIN   512
#define WIN   512
#define HOUT  510
#define WOUT  510
#define NB    16

// ---------------- tiling ----------------
#define TY      4              // output rows per CTA
#define TPX     64             // output px per CTA
#define XPX     68             // staged px (64 + 2 halo, padded)
#define THREADS 256

// smem layout (bytes): 6 input-row slots + weights, all rows 128B
#define XSLOT      (XPX * 128)          // 8704
#define W_OFF      (6 * XSLOT)          // 52224
#define W_BYTES    (288 * 128)          // 36864 (rows: kk*32+co)
#define SMEM_TOTAL (W_OFF + W_BYTES)    // 89088

__device__ __forceinline__ uint32_t smem_u32(const void* p) {
    uint32_t a;
    asm("{ .reg .u64 t; cvta.to.shared.u64 t, %1; cvt.u32.u64 %0, t; }"
        : "=r"(a) : "l"(p));
    return a;
}
#define SWZ128(o)  ((o) ^ (((o) >> 3) & 0x70))

#define STS128(addr, a, b, c, d) \
    asm volatile("st.shared.v4.b32 [%0], {%1,%2,%3,%4};" \
        :: "r"(addr), "r"(a), "r"(b), "r"(c), "r"(d) : "memory")

#define LDSM4(r0, r1, r2, r3, addr) \
    asm volatile("ldmatrix.sync.aligned.m8n8.x4.shared.b16 {%0,%1,%2,%3}, [%4];" \
        : "=r"(r0), "=r"(r1), "=r"(r2), "=r"(r3) : "r"(addr))

#define MMA16816(c0, c1, c2, c3, a0, a1, a2, a3, b0, b1) \
    asm volatile("mma.sync.aligned.m16n8k16.row.col.f32.bf16.bf16.f32 " \
        "{%0,%1,%2,%3}, {%4,%5,%6,%7}, {%8,%9}, {%0,%1,%2,%3};" \
        : "+f"(c0), "+f"(c1), "+f"(c2), "+f"(c3) \
        : "r"(a0), "r"(a1), "r"(a2), "r"(a3), "r"(b0), "r"(b1))

// pack two floats -> bf16x2 (arg order: {lo, hi} -> reg = hi<<16 | lo)
__device__ __forceinline__ uint32_t pack_bf2(float vhi, float vlo) {
    uint32_t r;
    asm("cvt.rn.bf16x2.f32 %0, %1, %2;" : "=r"(r) : "f"(vhi), "f"(vlo));
    return r;
}
// split 8 fp32 -> bf16 hi[4 x bf16x2] + lo[4 x bf16x2]
__device__ __forceinline__ void split8(const float* v, uint32_t* hp, uint32_t* lp) {
    #pragma unroll
    for (int j = 0; j < 8; j += 2) {
        uint32_t hpair = pack_bf2(v[j + 1], v[j]);
        float h0 = __uint_as_float(hpair << 16);
        float h1 = __uint_as_float(hpair & 0xffff0000u);
        hp[j >> 1] = hpair;
        lp[j >> 1] = pack_bf2(v[j + 1] - h1, v[j] - h0);
    }
}

__global__ __launch_bounds__(THREADS, 2)
void conv_mma_kernel(const float* __restrict__ x,
                     const float* __restrict__ w,
                     const float* __restrict__ bias,
                     float* __restrict__ out)
{
    extern __shared__ char smem[];
    const uint32_t sb = smem_u32(smem);
    const int t    = threadIdx.x;
    const int wid  = t >> 5;
    const int lane = t & 31;

    const int xt = blockIdx.x;       // 0..7
    const int yt = blockIdx.y;       // 0..127
    const int nb = blockIdx.z;       // 0..15
    const int x0 = xt * TPX;
    const int y0 = yt * TY;

    // ---- stage W: row = kk*32 + co, 128B = [32 ci hi | 32 ci lo] bf16, swizzled
    #pragma unroll 1
    for (int row = t; row < 288; row += THREADS) {
        const int kk = row >> 5;          // ky*3+kx
        const int co = row & 31;
        const float* wp = w + (size_t)co * 288 + kk;   // + ci*9
        const uint32_t base = sb + W_OFF;
        #pragma unroll
        for (int c0 = 0; c0 < CIN; c0 += 8) {
            float v[8];
            #pragma unroll
            for (int j = 0; j < 8; ++j) v[j] = wp[(size_t)(c0 + j) * 9];
            uint32_t hp[4], lp[4];
            split8(v, hp, lp);
            STS128(base + SWZ128((uint32_t)(row * 128 + c0 * 2)),      hp[0], hp[1], hp[2], hp[3]);
            STS128(base + SWZ128((uint32_t)(row * 128 + 64 + c0 * 2)), lp[0], lp[1], lp[2], lp[3]);
        }
    }

    // ---- stage X: 6 input rows x 68 px, row 128B = [ci hi | ci lo], swizzled
    #pragma unroll 1
    for (int idx = t; idx < 6 * XPX; idx += THREADS) {
        const int s  = idx / XPX;
        const int px = idx - s * XPX;
        const int y_in = y0 + s;
        const int ix   = x0 + px;
        const bool ok = (y_in < HIN) && (ix < WIN);
        const float* xp = x + ((size_t)(nb * CIN) * HIN + y_in) * WIN + ix;
        const uint32_t base = sb + s * XSLOT;
        #pragma unroll
        for (int c0 = 0; c0 < CIN; c0 += 8) {
            float v[8];
            #pragma unroll
            for (int j = 0; j < 8; ++j)
                v[j] = ok ? xp[(size_t)(c0 + j) * HIN * WIN] : 0.0f;
            uint32_t hp[4], lp[4];
            split8(v, hp, lp);
            STS128(base + SWZ128((uint32_t)(px * 128 + c0 * 2)),      hp[0], hp[1], hp[2], hp[3]);
            STS128(base + SWZ128((uint32_t)(px * 128 + 64 + c0 * 2)), lp[0], lp[1], lp[2], lp[3]);
        }
    }
    __syncthreads();

    // ---- warp tiles: 2 co-tiles x 4 px-tiles
    const int ct  = wid & 1;           // co tile (16 co)
    const int pxb = (wid >> 1) * 16;   // px base (16 px)

    // lane constants for ldmatrix fragment addressing
    const int l7      = lane & 7;
    const int a_row   = lane & 15;           // A: row within 16
    const int a_chunk = lane >> 4;           // A: 16B chunk 0/1
    const int b_n     = (lane & 7) | ((lane >> 4) << 3);   // B: px within 16
    const int b_chunk = (lane >> 3) & 1;                   // B: 16B chunk 0/1

    const uint32_t Wb = sb + W_OFF + (uint32_t)(ct * 16 + a_row) * 128;

    const int g  = lane >> 2;
    const int tg = lane & 3;
    const float bias0 = __ldg(bias + ct * 16 + g);
    const float bias1 = __ldg(bias + ct * 16 + 8 + g);

    // split combos: (w_lo?, x_lo?) : hh, lh, hl
    const int wlo_t[3] = {0, 1, 0};
    const int xlo_t[3] = {0, 0, 1};

    #pragma unroll 1
    for (int r = 0; r < TY; ++r) {
        float c[2][4];
        #pragma unroll
        for (int j = 0; j < 2; ++j) {
            c[j][0] = bias0; c[j][1] = bias0;
            c[j][2] = bias1; c[j][3] = bias1;
        }

        #pragma unroll
        for (int ky = 0; ky < 3; ++ky) {
            const uint32_t Xs = sb + (uint32_t)(r + ky) * XSLOT;
            #pragma unroll
            for (int kx = 0; kx < 3; ++kx) {
                const int kk = ky * 3 + kx;
                const uint32_t aRow = Wb + (uint32_t)kk * 4096;
                const uint32_t bRow = Xs + (uint32_t)(pxb + kx + b_n) * 128;
                const int bx7 = (kx + b_n) & 7;

                #pragma unroll
                for (int cb = 0; cb < 3; ++cb) {
                    #pragma unroll
                    for (int h = 0; h < 2; ++h) {
                        const int wc = wlo_t[cb] * 4 + h * 2 + a_chunk;
                        const int xc = xlo_t[cb] * 4 + h * 2 + b_chunk;
                        const uint32_t aAddr = aRow + (uint32_t)((wc ^ l7) << 4);
                        const uint32_t bAddr = bRow + (uint32_t)((xc ^ bx7) << 4);

                        uint32_t a0, a1, a2, a3, e0, e1, e2, e3;
                        LDSM4(a0, a1, a2, a3, aAddr);
                        LDSM4(e0, e1, e2, e3, bAddr);
                        MMA16816(c[0][0], c[0][1], c[0][2], c[0][3],
                                 a0, a1, a2, a3, e0, e1);
                        MMA16816(c[1][0], c[1][1], c[1][2], c[1][3],
                                 a0, a1, a2, a3, e2, e3);
                    }
                }
            }
        }

        // ---- store row r (fp32, float2 per n-tile, guarded at edges)
        const int oy = y0 + r;
        if (oy < HOUT) {
            const size_t base0 =
                ((size_t)(nb * COUT + ct * 16 + g) * HOUT + oy) * (size_t)WOUT;
            const size_t coStep = (size_t)8 * HOUT * WOUT;
            #pragma unroll
            for (int j = 0; j < 2; ++j) {
                const int ox = x0 + pxb + j * 8 + 2 * tg;
                if (ox < WOUT) {
                    float2 v0 = make_float2(c[j][0], c[j][1]);
                    float2 v1 = make_float2(c[j][2], c[j][3]);
                    *reinterpret_cast<float2*>(out + base0 + ox)          = v0;
                    *reinterpret_cast<float2*>(out + base0 + coStep + ox) = v1;
                }
            }
        }
    }
}

extern "C" void kernel_launch(void* const* d_in, const int* in_sizes, int n_in,
                              void* d_out, int out_size)
{
    const float* x    = (const float*)d_in[0];
    const float* w    = (const float*)d_in[1];
    const float* bias = (const float*)d_in[2];
    float*       out  = (float*)d_out;

    cudaFuncSetAttribute(conv_mma_kernel,
                         cudaFuncAttributeMaxDynamicSharedMemorySize, SMEM_TOTAL);

    dim3 grid((WOUT + TPX - 1) / TPX,   // 8
              (HOUT + TY - 1) / TY,     // 128
              NB);                      // 16
    conv_mma_kernel<<<grid, THREADS, SMEM_TOTAL>>>(x, w, bias, out);
}

// round 6
// speedup vs baseline: 2.2982x; 1.1854x over previous
#include <cuda_runtime.h>
#include <cuda_bf16.h>
#include <cstdint>

// ---------------- problem dims ----------------
#define CIN   32
#define COUT  32
#define HIN   512
#define WIN   512
#define HOUT  510
#define WOUT  510
#define NB    16

// ---------------- tiling ----------------
#define TY      4              // output rows per CTA (1 row per warp, 2 px-chunks)
#define TPX     64             // output px per CTA
#define XPX     68             // staged px (64 + 2 halo, padded)
#define THREADS 256

// smem layout (bytes): 6 input-row slots + weights, all rows 128B
#define XSLOT      (XPX * 128)          // 8704
#define W_OFF      (6 * XSLOT)          // 52224
#define W_BYTES    (288 * 128)          // 36864 (rows: kk*32+co)
#define SMEM_TOTAL (W_OFF + W_BYTES)    // 89088

__device__ __forceinline__ uint32_t smem_u32(const void* p) {
    uint32_t a;
    asm("{ .reg .u64 t; cvta.to.shared.u64 t, %1; cvt.u32.u64 %0, t; }"
        : "=r"(a) : "l"(p));
    return a;
}
#define SWZ128(o)  ((o) ^ (((o) >> 3) & 0x70))

#define STS128(addr, a, b, c, d) \
    asm volatile("st.shared.v4.b32 [%0], {%1,%2,%3,%4};" \
        :: "r"(addr), "r"(a), "r"(b), "r"(c), "r"(d) : "memory")

#define LDSM4(r0, r1, r2, r3, addr) \
    asm volatile("ldmatrix.sync.aligned.m8n8.x4.shared.b16 {%0,%1,%2,%3}, [%4];" \
        : "=r"(r0), "=r"(r1), "=r"(r2), "=r"(r3) : "r"(addr))

#define MMA16816(c, a, b0, b1) \
    asm volatile("mma.sync.aligned.m16n8k16.row.col.f32.bf16.bf16.f32 " \
        "{%0,%1,%2,%3}, {%4,%5,%6,%7}, {%8,%9}, {%0,%1,%2,%3};" \
        : "+f"((c)[0]), "+f"((c)[1]), "+f"((c)[2]), "+f"((c)[3]) \
        : "r"((a)[0]), "r"((a)[1]), "r"((a)[2]), "r"((a)[3]), "r"(b0), "r"(b1))

// pack two floats -> bf16x2
__device__ __forceinline__ uint32_t pack_bf2(float vhi, float vlo) {
    uint32_t r;
    asm("cvt.rn.bf16x2.f32 %0, %1, %2;" : "=r"(r) : "f"(vhi), "f"(vlo));
    return r;
}
// split 8 fp32 -> bf16 hi[4 x bf16x2] + lo[4 x bf16x2]
__device__ __forceinline__ void split8(const float* v, uint32_t* hp, uint32_t* lp) {
    #pragma unroll
    for (int j = 0; j < 8; j += 2) {
        uint32_t hpair = pack_bf2(v[j + 1], v[j]);
        float h0 = __uint_as_float(hpair << 16);
        float h1 = __uint_as_float(hpair & 0xffff0000u);
        hp[j >> 1] = hpair;
        lp[j >> 1] = pack_bf2(v[j + 1] - h1, v[j] - h0);
    }
}

__global__ __launch_bounds__(THREADS, 2)
void conv_mma_kernel(const float* __restrict__ x,
                     const float* __restrict__ w,
                     const float* __restrict__ bias,
                     float* __restrict__ out)
{
    extern __shared__ char smem[];
    const uint32_t sb = smem_u32(smem);
    const int t    = threadIdx.x;
    const int wid  = t >> 5;
    const int lane = t & 31;

    const int xt = blockIdx.x;       // 0..7
    const int yt = blockIdx.y;       // 0..127
    const int nb = blockIdx.z;       // 0..15
    const int x0 = xt * TPX;
    const int y0 = yt * TY;

    // ---- stage W: row = kk*32 + co, 128B = [32 ci hi | 32 ci lo] bf16, swizzled
    #pragma unroll 1
    for (int row = t; row < 288; row += THREADS) {
        const int kk = row >> 5;          // ky*3+kx
        const int co = row & 31;
        const float* wp = w + (size_t)co * 288 + kk;   // + ci*9
        const uint32_t base = sb + W_OFF;
        #pragma unroll
        for (int c0 = 0; c0 < CIN; c0 += 8) {
            float v[8];
            #pragma unroll
            for (int j = 0; j < 8; ++j) v[j] = wp[(size_t)(c0 + j) * 9];
            uint32_t hp[4], lp[4];
            split8(v, hp, lp);
            STS128(base + SWZ128((uint32_t)(row * 128 + c0 * 2)),      hp[0], hp[1], hp[2], hp[3]);
            STS128(base + SWZ128((uint32_t)(row * 128 + 64 + c0 * 2)), lp[0], lp[1], lp[2], lp[3]);
        }
    }

    // ---- stage X: 6 input rows x 68 px, row 128B = [ci hi | ci lo], swizzled
    #pragma unroll 1
    for (int idx = t; idx < 6 * XPX; idx += THREADS) {
        const int s  = idx / XPX;
        const int px = idx - s * XPX;
        const int y_in = y0 + s;
        const int ix   = x0 + px;
        const bool ok = (y_in < HIN) && (ix < WIN);
        const float* xp = x + ((size_t)(nb * CIN) * HIN + y_in) * WIN + ix;
        const uint32_t base = sb + s * XSLOT;
        #pragma unroll
        for (int c0 = 0; c0 < CIN; c0 += 8) {
            float v[8];
            #pragma unroll
            for (int j = 0; j < 8; ++j)
                v[j] = ok ? xp[(size_t)(c0 + j) * HIN * WIN] : 0.0f;
            uint32_t hp[4], lp[4];
            split8(v, hp, lp);
            STS128(base + SWZ128((uint32_t)(px * 128 + c0 * 2)),      hp[0], hp[1], hp[2], hp[3]);
            STS128(base + SWZ128((uint32_t)(px * 128 + 64 + c0 * 2)), lp[0], lp[1], lp[2], lp[3]);
        }
    }
    __syncthreads();

    // ---- warp tile: all 32 co x 32 px, one output row per warp
    const int r   = wid >> 1;          // output row 0..3
    const int pxw = (wid & 1) * 32;    // px chunk base

    // lane constants for ldmatrix fragment addressing
    const int l7      = lane & 7;
    const int a_row   = lane & 15;           // A: row within m16
    const int a_chunk = lane >> 4;           // A: 16B chunk 0/1
    const int b_n     = (lane & 7) | ((lane >> 4) << 3);   // B: px within 16
    const int b_chunk = (lane >> 3) & 1;                   // B: 16B chunk 0/1

    const int g  = lane >> 2;
    const int tg = lane & 3;

    // accumulators: c[mt][nt][4]  (mt: co 16-halves, nt: px 8-groups)
    float c[2][4][4];
    #pragma unroll
    for (int mt = 0; mt < 2; ++mt) {
        const float bv0 = __ldg(bias + mt * 16 + g);
        const float bv1 = __ldg(bias + mt * 16 + 8 + g);
        #pragma unroll
        for (int nt = 0; nt < 4; ++nt) {
            c[mt][nt][0] = bv0; c[mt][nt][1] = bv0;
            c[mt][nt][2] = bv1; c[mt][nt][3] = bv1;
        }
    }

    #pragma unroll
    for (int ky = 0; ky < 3; ++ky) {
        const uint32_t Xs = sb + (uint32_t)(r + ky) * XSLOT;
        #pragma unroll
        for (int kx = 0; kx < 3; ++kx) {
            const int kk = ky * 3 + kx;
            const uint32_t aRow0 = sb + W_OFF + (uint32_t)kk * 4096 + (uint32_t)a_row * 128;
            const uint32_t aRow1 = aRow0 + 16 * 128;
            const int brow = pxw + kx + b_n;
            const uint32_t bRow0 = Xs + (uint32_t)brow * 128;
            const uint32_t bRow1 = bRow0 + 16 * 128;
            const int bx7 = brow & 7;

            #pragma unroll
            for (int h = 0; h < 2; ++h) {           // ci half (k16 each)
                const uint32_t aoH = (uint32_t)(((h * 2 + a_chunk) ^ l7) << 4);
                const uint32_t aoL = (uint32_t)(((h * 2 + a_chunk + 4) ^ l7) << 4);
                const uint32_t boH = (uint32_t)(((h * 2 + b_chunk) ^ bx7) << 4);
                const uint32_t boL = (uint32_t)(((h * 2 + b_chunk + 4) ^ bx7) << 4);

                uint32_t ah[2][4], al[2][4], bh[2][4], bl[2][4];
                LDSM4(ah[0][0], ah[0][1], ah[0][2], ah[0][3], aRow0 + aoH);
                LDSM4(ah[1][0], ah[1][1], ah[1][2], ah[1][3], aRow1 + aoH);
                LDSM4(bh[0][0], bh[0][1], bh[0][2], bh[0][3], bRow0 + boH);
                LDSM4(bh[1][0], bh[1][1], bh[1][2], bh[1][3], bRow1 + boH);
                LDSM4(bl[0][0], bl[0][1], bl[0][2], bl[0][3], bRow0 + boL);
                LDSM4(bl[1][0], bl[1][1], bl[1][2], bl[1][3], bRow1 + boL);
                LDSM4(al[0][0], al[0][1], al[0][2], al[0][3], aRow0 + aoL);
                LDSM4(al[1][0], al[1][1], al[1][2], al[1][3], aRow1 + aoL);

                #pragma unroll
                for (int mt = 0; mt < 2; ++mt) {
                    #pragma unroll
                    for (int nt = 0; nt < 4; ++nt) {
                        const int q  = nt >> 1;
                        const int e0 = (nt & 1) * 2;
                        // hh
                        MMA16816(c[mt][nt], ah[mt], bh[q][e0], bh[q][e0 + 1]);
                        // hl: A_hi * B_lo
                        MMA16816(c[mt][nt], ah[mt], bl[q][e0], bl[q][e0 + 1]);
                        // lh: A_lo * B_hi
                        MMA16816(c[mt][nt], al[mt], bh[q][e0], bh[q][e0 + 1]);
                    }
                }
            }
        }
    }

    // ---- store (fp32, float2 per n-tile, guarded at edges)
    const int oy = y0 + r;
    if (oy < HOUT) {
        #pragma unroll
        for (int mt = 0; mt < 2; ++mt) {
            const size_t base0 =
                ((size_t)(nb * COUT + mt * 16 + g) * HOUT + oy) * (size_t)WOUT;
            const size_t coStep = (size_t)8 * HOUT * WOUT;
            #pragma unroll
            for (int nt = 0; nt < 4; ++nt) {
                const int ox = x0 + pxw + nt * 8 + 2 * tg;
                if (ox < WOUT) {
                    float2 v0 = make_float2(c[mt][nt][0], c[mt][nt][1]);
                    float2 v1 = make_float2(c[mt][nt][2], c[mt][nt][3]);
                    *reinterpret_cast<float2*>(out + base0 + ox)          = v0;
                    *reinterpret_cast<float2*>(out + base0 + coStep + ox) = v1;
                }
            }
        }
    }
}

extern "C" void kernel_launch(void* const* d_in, const int* in_sizes, int n_in,
                              void* d_out, int out_size)
{
    const float* x    = (const float*)d_in[0];
    const float* w    = (const float*)d_in[1];
    const float* bias = (const float*)d_in[2];
    float*       out  = (float*)d_out;

    cudaFuncSetAttribute(conv_mma_kernel,
                         cudaFuncAttributeMaxDynamicSharedMemorySize, SMEM_TOTAL);

    dim3 grid((WOUT + TPX - 1) / TPX,   // 8
              (HOUT + TY - 1) / TY,     // 128
              NB);                      // 16
    conv_mma_kernel<<<grid, THREADS, SMEM_TOTAL>>>(x, w, bias, out);
}